// round 17
// baseline (speedup 1.0000x reference)
#include <cuda_runtime.h>
#include <cstdint>

// Problem constants
#define BB 8
#define TT 200
#define UU 100
#define EE 512
#define PP 640
#define HH 512
#define VV 1024
#define TUU (TT * UU)          // 20000
#define MTOT (BB * TUU)        // 160000

// Scratch (no cudaMalloc allowed)
__device__ float g_enc[BB * TT * HH];   // 1600 x 512
__device__ float g_pred[BB * UU * HH];  //  800 x 512

// ===========================================================================
// Helpers
// ===========================================================================
__device__ __forceinline__ uint32_t smem_u32(const void* p) {
    uint32_t a;
    asm("{ .reg .u64 t; cvta.to.shared.u64 t, %1; cvt.u32.u64 %0, t; }"
        : "=r"(a) : "l"(p));
    return a;
}

__device__ __forceinline__ unsigned f2tf32(float x) {
    unsigned r;
    asm("cvt.rna.tf32.f32 %0, %1;" : "=r"(r) : "f"(x));
    return r;
}

__device__ __forceinline__ void mma_tf32(float* c, const unsigned* a,
                                         unsigned b0, unsigned b1) {
    asm volatile(
        "mma.sync.aligned.m16n8k8.row.col.f32.tf32.tf32.f32 "
        "{%0,%1,%2,%3}, {%4,%5,%6,%7}, {%8,%9}, {%0,%1,%2,%3};\n"
        : "+f"(c[0]), "+f"(c[1]), "+f"(c[2]), "+f"(c[3])
        : "r"(a[0]), "r"(a[1]), "r"(a[2]), "r"(a[3]), "r"(b0), "r"(b1));
}

__device__ __forceinline__ void cp_async16(uint32_t dst, const void* src) {
    asm volatile(
        "{ .reg .u64 g; cvta.to.global.u64 g, %1;"
        "  cp.async.cg.shared.global [%0], [g], 16; }"
        :: "r"(dst), "l"(src) : "memory");
}
#define CP_COMMIT() asm volatile("cp.async.commit_group;" ::: "memory")
#define CP_WAIT0()  asm volatile("cp.async.wait_group 0;" ::: "memory")
#define CP_WAIT1()  asm volatile("cp.async.wait_group 1;" ::: "memory")

// ===========================================================================
// Phase 1: both projections in one launch (z=0: enc, z=1: pred)
// ===========================================================================
__global__ __launch_bounds__(256) void proj_both_kernel(
    const float* __restrict__ encX, const float* __restrict__ Wenc,
    const float* __restrict__ benc, float* __restrict__ encY,
    const float* __restrict__ predX, const float* __restrict__ Wpred,
    const float* __restrict__ bpred, float* __restrict__ predY)
{
    const int z = blockIdx.z;
    const float* X = z ? predX : encX;
    const float* W = z ? Wpred : Wenc;
    const float* bias = z ? bpred : benc;
    float* Y = z ? predY : encY;
    const int M = z ? (BB * UU) : (BB * TT);
    const int K = z ? PP : EE;
    const int N = HH;

    const int mBase = blockIdx.y * 64;
    if (mBase >= M) return;
    const int nBase = blockIdx.x * 64;

    __shared__ float Xs[16][68];
    __shared__ float Ws[16][68];

    const int tx = threadIdx.x;
    const int ty = threadIdx.y;
    const int tid = ty * 16 + tx;
    const int lm = tid & 63;
    const int kq = (tid >> 6) * 4;

    float acc[4][4];
#pragma unroll
    for (int i = 0; i < 4; i++)
#pragma unroll
        for (int j = 0; j < 4; j++) acc[i][j] = 0.f;

    for (int k0 = 0; k0 < K; k0 += 16) {
        float4 xv = make_float4(0.f, 0.f, 0.f, 0.f);
        const int row = mBase + lm;
        if (row < M)
            xv = *(const float4*)(X + (size_t)row * K + k0 + kq);
        Xs[kq + 0][lm] = xv.x; Xs[kq + 1][lm] = xv.y;
        Xs[kq + 2][lm] = xv.z; Xs[kq + 3][lm] = xv.w;

        float4 wv = *(const float4*)(W + (size_t)(nBase + lm) * K + k0 + kq);
        Ws[kq + 0][lm] = wv.x; Ws[kq + 1][lm] = wv.y;
        Ws[kq + 2][lm] = wv.z; Ws[kq + 3][lm] = wv.w;

        __syncthreads();
#pragma unroll
        for (int kk = 0; kk < 16; kk++) {
            float4 a = *(const float4*)&Xs[kk][ty * 4];
            float4 b = *(const float4*)&Ws[kk][tx * 4];
            float av[4] = {a.x, a.y, a.z, a.w};
            float bv[4] = {b.x, b.y, b.z, b.w};
#pragma unroll
            for (int i = 0; i < 4; i++)
#pragma unroll
                for (int j = 0; j < 4; j++)
                    acc[i][j] = fmaf(av[i], bv[j], acc[i][j]);
        }
        __syncthreads();
    }

    float4 bb = *(const float4*)(bias + nBase + tx * 4);
    float bv[4] = {bb.x, bb.y, bb.z, bb.w};
#pragma unroll
    for (int i = 0; i < 4; i++) {
        const int row = mBase + ty * 4 + i;
        if (row < M) {
            float4 o;
            o.x = acc[i][0] + bv[0]; o.y = acc[i][1] + bv[1];
            o.z = acc[i][2] + bv[2]; o.w = acc[i][3] + bv[3];
            *(float4*)(Y + (size_t)row * N + nBase + tx * 4) = o;
        }
    }
}

// ===========================================================================
// Phase 2: fused joint GEMM — two-stage pipeline, TWO barriers per chunk.
//   CTA 64(M) x 256(N), 256 threads, K-chunk 32, warp tile 32x64, occ 2.
//   end-sync(it-1) separates MMA(it-1) from ISSUE_B(it) on the shared stage;
//   mid-sync(it) (after CP_WAIT) publishes cp.async B + A stores before MMA.
// Dynamic smem: As 2x(64*SA) + Bs 2x(256*SB) + offsets = 92672 B (occ 2 fits)
// ===========================================================================
#define SA 36
#define SB 36
#define A_STG (64 * SA)          // 2304 words
#define B_STG (256 * SB)         // 9216 words
#define JSMEM_TOT ((2 * A_STG + 2 * B_STG + 128) * 4)   // 92672 B

__global__ __launch_bounds__(256, 2) void joint_mma_kernel(
    const float* __restrict__ Wout, const float* __restrict__ bout,
    float* __restrict__ out)
{
    extern __shared__ unsigned dsm[];
    unsigned* As = dsm;                       // [2][64*SA]
    unsigned* Bs = dsm + 2 * A_STG;           // [2][256*SB]
    int* encOff  = (int*)(dsm + 2 * A_STG + 2 * B_STG);
    int* predOff = encOff + 64;

    const int tid = threadIdx.x;
    const int mBase = blockIdx.x * 64;
    const int vBase = blockIdx.y * 256;

    if (tid < 64) {
        const int gm = mBase + tid;
        const int b = gm / TUU;
        const int r = gm % TUU;
        const int t = r / UU;
        const int u = r % UU;
        encOff[tid] = (b * TT + t) * HH;
        predOff[tid] = (b * UU + u) * HH;
    }
    __syncthreads();

    const int lane = tid & 31;
    const int warp = tid >> 5;
    const int warpM = (warp & 1) * 32;      // 0 or 32
    const int warpN = (warp >> 1) * 64;     // 0,64,128,192
    const int gID = lane >> 2;              // 0..7
    const int t4 = lane & 3;                // 0..3

    // A-fill mapping (verified): each thread covers 8 k of one m-row
    const int am = tid >> 2;                // 0..63
    const int akq = (tid & 3) * 8;          // 0,8,16,24
    const float* encP = g_enc + encOff[am] + akq;
    const float* predP = g_pred + predOff[am] + akq;
    const int aWrIdx = am * SA + akq;       // within-stage word index

    // B-fill mapping (verified): 8 lanes per W_out row, 8 passes
    const int bn = tid >> 3;                // 0..31
    const int bkk = (tid & 7) * 4;          // 0..28
    const float* bsrc = Wout + (size_t)(vBase + bn) * HH + bkk;
    const uint32_t bDst[2] = {
        smem_u32(&Bs[0 * B_STG + bn * SB + bkk]),
        smem_u32(&Bs[1 * B_STG + bn * SB + bkk])
    };

    float acc[2][8][4];
#pragma unroll
    for (int mt = 0; mt < 2; mt++)
#pragma unroll
        for (int nt = 0; nt < 8; nt++)
#pragma unroll
            for (int i = 0; i < 4; i++) acc[mt][nt][i] = 0.f;

#define STORE_A(stg, e0, e1, p0, p1) do {                                     \
    uint4 v0, v1;                                                             \
    v0.x = f2tf32(fmaxf(e0.x + p0.x, 0.f));                                   \
    v0.y = f2tf32(fmaxf(e0.y + p0.y, 0.f));                                   \
    v0.z = f2tf32(fmaxf(e0.z + p0.z, 0.f));                                   \
    v0.w = f2tf32(fmaxf(e0.w + p0.w, 0.f));                                   \
    v1.x = f2tf32(fmaxf(e1.x + p1.x, 0.f));                                   \
    v1.y = f2tf32(fmaxf(e1.y + p1.y, 0.f));                                   \
    v1.z = f2tf32(fmaxf(e1.z + p1.z, 0.f));                                   \
    v1.w = f2tf32(fmaxf(e1.w + p1.w, 0.f));                                   \
    *(uint4*)&As[(stg) * A_STG + aWrIdx] = v0;                                \
    *(uint4*)&As[(stg) * A_STG + aWrIdx + 4] = v1;                            \
} while (0)

#define ISSUE_B(stg, K0) do {                                                 \
    _Pragma("unroll")                                                         \
    for (int p = 0; p < 8; p++)                                               \
        cp_async16(bDst[stg] + (uint32_t)(p * 32 * SB * 4),                   \
                   bsrc + (K0) + (size_t)p * 32 * HH);                        \
    CP_COMMIT();                                                              \
} while (0)

    // ---- prologue: fill stage 0 (chunk 0) ----
    {
        float4 e0 = *(const float4*)(encP);
        float4 e1 = *(const float4*)(encP + 4);
        float4 p0 = *(const float4*)(predP);
        float4 p1 = *(const float4*)(predP + 4);
        STORE_A(0, e0, e1, p0, p1);
    }
    ISSUE_B(0, 0);

    int st = 0;
    for (int it = 0; it < 16; it++) {
        const int nxt = st ^ 1;

        // issue next chunk's B + prefetch next A into regs.
        // SAFE: end-sync of iteration it-1 guarantees no warp still reads
        // stage nxt (= stage consumed at it-1).
        float4 e0, e1, p0, p1;
        if (it < 15) {
            const int k0n = (it + 1) * 32;
            e0 = *(const float4*)(encP + k0n);
            e1 = *(const float4*)(encP + k0n + 4);
            p0 = *(const float4*)(predP + k0n);
            p1 = *(const float4*)(predP + k0n + 4);
            ISSUE_B(nxt, k0n);
            CP_WAIT1();    // stage st's B group complete (issued last iter)
        } else {
            CP_WAIT0();
        }
        __syncthreads();   // publish cp.async B + prev-iter A stores

        // ---- 4 x k8 MMA steps on stage st (verified addressing) ----
        const unsigned* Ac = As + st * A_STG;
        const unsigned* Bc = Bs + st * B_STG;
#pragma unroll
        for (int s = 0; s < 4; s++) {
            const int kk = s * 8;
            unsigned a[2][4];
#pragma unroll
            for (int mt = 0; mt < 2; mt++) {
                const int rb = (warpM + mt * 16 + gID) * SA + kk + t4;
                a[mt][0] = Ac[rb];
                a[mt][1] = Ac[rb + 8 * SA];
                a[mt][2] = Ac[rb + 4];
                a[mt][3] = Ac[rb + 8 * SA + 4];
            }
#pragma unroll
            for (int nt = 0; nt < 8; nt++) {
                const int nb = (warpN + nt * 8 + gID) * SB + kk + t4;
                const unsigned b0 = Bc[nb];
                const unsigned b1 = Bc[nb + 4];
                mma_tf32(acc[0][nt], a[0], b0, b1);
                mma_tf32(acc[1][nt], a[1], b0, b1);
            }
        }

        // store next chunk's A into the other stage (disjoint buffer)
        if (it < 15)
            STORE_A(nxt, e0, e1, p0, p1);

        // END barrier: all warps done reading stage st before the next
        // iteration's ISSUE_B overwrites it. (This was the R16 race.)
        __syncthreads();

        st = nxt;
    }

    // ---- epilogue: (acc + b_out) * 0.1, fp32 out ----
#pragma unroll
    for (int mt = 0; mt < 2; mt++) {
        const int row0 = mBase + warpM + mt * 16 + gID;
#pragma unroll
        for (int nt = 0; nt < 8; nt++) {
            const int v = vBase + warpN + nt * 8 + t4 * 2;
            const float bo0 = __ldg(bout + v);
            const float bo1 = __ldg(bout + v + 1);
            float2 r0, r1;
            r0.x = (acc[mt][nt][0] + bo0) * 0.1f;
            r0.y = (acc[mt][nt][1] + bo1) * 0.1f;
            r1.x = (acc[mt][nt][2] + bo0) * 0.1f;
            r1.y = (acc[mt][nt][3] + bo1) * 0.1f;
            *(float2*)(out + (size_t)row0 * VV + v) = r0;
            *(float2*)(out + (size_t)(row0 + 8) * VV + v) = r1;
        }
    }
}

// ===========================================================================
// Launch
// ===========================================================================
extern "C" void kernel_launch(void* const* d_in, const int* in_sizes, int n_in,
                              void* d_out, int out_size)
{
    (void)in_sizes; (void)n_in; (void)out_size;
    const float* enc_in  = (const float*)d_in[0];
    const float* pred_in = (const float*)d_in[1];
    const float* W_enc   = (const float*)d_in[2];
    const float* b_enc   = (const float*)d_in[3];
    const float* W_pred  = (const float*)d_in[4];
    const float* b_pred  = (const float*)d_in[5];
    const float* W_out   = (const float*)d_in[6];
    const float* b_out   = (const float*)d_in[7];
    float* out = (float*)d_out;

    void* p;
    cudaGetSymbolAddress(&p, g_enc);
    float* enc = (float*)p;
    cudaGetSymbolAddress(&p, g_pred);
    float* pred = (float*)p;

    proj_both_kernel<<<dim3(HH / 64, 25, 2), dim3(16, 16)>>>(
        enc_in, W_enc, b_enc, enc, pred_in, W_pred, b_pred, pred);

    cudaFuncSetAttribute(joint_mma_kernel,
                         cudaFuncAttributeMaxDynamicSharedMemorySize, JSMEM_TOT);
    joint_mma_kernel<<<dim3(MTOT / 64, VV / 256), 256, JSMEM_TOT>>>(
        W_out, b_out, out);
}